// round 9
// baseline (speedup 1.0000x reference)
#include <cuda_runtime.h>
#include <cuda_bf16.h>
#include <stdint.h>

#define BROWS 256
#define DDIM  1024
#define HDIM  2048
#define NOUT  2048   // 2*D

// ---------------- scratch (__device__ globals; no allocation allowed) ----------
__device__ float          g_mu[BROWS * DDIM];
__device__ __nv_bfloat16  g_mubf[BROWS * DDIM];
__device__ __nv_bfloat16  g_w1bf[DDIM * HDIM];   // [k=1024][n=2048]
__device__ __nv_bfloat16  g_w2bf[HDIM * NOUT];   // [k=2048][n=2048]
__device__ __nv_bfloat16  g_h[BROWS * HDIM];
__device__ float          g_out[BROWS * NOUT];
__device__ float g_invg[BROWS], g_r[BROWS], g_wgt[BROWS];
__device__ int   g_lowt[BROWS];
__device__ float g_partial[1024];

// ---------------- PTX helpers ----------------------------------------------------
__device__ __forceinline__ uint32_t cvta_shared_u32(const void* p) {
    uint32_t a;
    asm("{ .reg .u64 t; cvta.to.shared.u64 t, %1; cvt.u32.u64 %0, t; }"
        : "=r"(a) : "l"(p));
    return a;
}
__device__ __forceinline__ void cpa16(uint32_t dst, const void* src) {
    asm volatile("cp.async.cg.shared.global [%0], [%1], 16;\n" :: "r"(dst), "l"(src));
}
__device__ __forceinline__ void ldm_x4(uint32_t* r, uint32_t addr) {
    asm volatile("ldmatrix.sync.aligned.m8n8.x4.shared.b16 {%0,%1,%2,%3}, [%4];\n"
                 : "=r"(r[0]), "=r"(r[1]), "=r"(r[2]), "=r"(r[3]) : "r"(addr));
}
__device__ __forceinline__ void ldm_x4t(uint32_t* r, uint32_t addr) {
    asm volatile("ldmatrix.sync.aligned.m8n8.x4.trans.shared.b16 {%0,%1,%2,%3}, [%4];\n"
                 : "=r"(r[0]), "=r"(r[1]), "=r"(r[2]), "=r"(r[3]) : "r"(addr));
}
__device__ __forceinline__ void mma16816(float* c, const uint32_t* a, const uint32_t* b) {
    asm volatile(
        "mma.sync.aligned.m16n8k16.row.col.f32.bf16.bf16.f32 "
        "{%0,%1,%2,%3}, {%4,%5,%6,%7}, {%8,%9}, {%0,%1,%2,%3};\n"
        : "+f"(c[0]), "+f"(c[1]), "+f"(c[2]), "+f"(c[3])
        : "r"(a[0]), "r"(a[1]), "r"(a[2]), "r"(a[3]), "r"(b[0]), "r"(b[1]));
}

// ---------------- fast erf (Abramowitz-Stegun 7.1.26, |err| <= 1.5e-7) ----------
__device__ __forceinline__ float erf_fast_e(float x, float e /* = exp(-x*x) */) {
    float ax = fabsf(x);
    float t = __fdividef(1.0f, fmaf(0.3275911f, ax, 1.0f));
    float p = fmaf(fmaf(fmaf(fmaf(1.061405429f, t, -1.453152027f), t,
                             1.421413741f), t, -0.284496736f), t, 0.254829592f) * t;
    return copysignf(1.0f - p * e, x);
}
__device__ __forceinline__ float erf_fast(float x) {
    return erf_fast_e(x, __expf(-x * x));
}

// ---------------- convert helper: 8 fp32 -> 8 bf16 per thread --------------------
__device__ __forceinline__ void conv8(const float* __restrict__ src,
                                      __nv_bfloat16* __restrict__ dst, int i) {
    float4 v0 = ((const float4*)src)[2 * i];
    float4 v1 = ((const float4*)src)[2 * i + 1];
    __nv_bfloat162 o[4];
    o[0] = __floats2bfloat162_rn(v0.x, v0.y);
    o[1] = __floats2bfloat162_rn(v0.z, v0.w);
    o[2] = __floats2bfloat162_rn(v1.x, v1.y);
    o[3] = __floats2bfloat162_rn(v1.z, v1.w);
    ((uint4*)dst)[i] = *(uint4*)o;
}

// ---------------- prep: mu + row scalars + W1 convert (W2 rides inside gemm1) ----
__global__ void __launch_bounds__(256) prep_k(const float* __restrict__ x,
                                              const float* __restrict__ noise,
                                              const float* __restrict__ t,
                                              const float* __restrict__ W1) {
    int blk = blockIdx.x;
    if (blk < 1024) {
        int i = blk * 256 + threadIdx.x;      // < 262144
        int b = i >> 10;
        float tv = __ldg(&t[b]);
        float sg = expf(-7.824046010856292f * tv);
        float gamma = 1.0f - sg;
        float mu = gamma * x[i] + gamma * sg * noise[i];
        g_mu[i]   = mu;
        g_mubf[i] = __float2bfloat16(mu);
        if (blk == 0 && threadIdx.x < BROWS) {
            int bb = threadIdx.x;
            float tb = t[bb];
            float s2 = expf(-7.824046010856292f * tb);
            float g2 = 1.0f - s2;
            g_invg[bb] = 1.0f / g2;
            g_r[bb]    = sqrtf(s2 / g2);
            g_wgt[bb]  = 1.0f / s2;
            g_lowt[bb] = (tb < 1e-10f) ? 1 : 0;
        }
        return;
    }
    conv8(W1, g_w1bf, (blk - 1024) * 256 + threadIdx.x);   // W1: 2M elems
}

// ---------------- GEMM: BM=BN=BK=64, 256 thr (8 warps 2x4, warp tile 32x16) ------
// MODE 1: 1D grid. blocks [0,128): C = mubf @ w1bf, epi +b1 + t*W1last, leaky -> g_h
//         blocks [128, 2176): piggyback W2 fp32->bf16 convert (fills idle SMs)
// MODE 2: 2D grid (32,4). C = h @ w2bf, epi +b2 -> g_out (fp32)
#define PITCH_B 144
#define STAGE_A (64 * PITCH_B)
#define STAGE_BYTES (2 * 64 * PITCH_B)
#define NSTAGE 3

template <int MODE>
__global__ void __launch_bounds__(256) gemm_k(int Kdim,
                                              const float* __restrict__ bias,
                                              const float* __restrict__ tvec,
                                              const float* __restrict__ w1last,
                                              const float* __restrict__ W2src) {
    int m0, n0;
    if (MODE == 1) {
        int blk = blockIdx.x;
        if (blk >= 128) {    // converter block: stream W2 fp32 -> bf16, then exit
            conv8(W2src, g_w2bf, (blk - 128) * 256 + threadIdx.x);
            return;
        }
        n0 = (blk & 31) * 64;
        m0 = (blk >> 5) * 64;
    } else {
        n0 = blockIdx.x * 64;
        m0 = blockIdx.y * 64;
    }

    extern __shared__ char smem[];
    uint32_t sbase = cvta_shared_u32(smem);

    const __nv_bfloat16* A = (MODE == 1) ? g_mubf : g_h;
    const __nv_bfloat16* B = (MODE == 1) ? g_w1bf : g_w2bf;

    int tid = threadIdx.x, wid = tid >> 5, lane = tid & 31;
    int wm = (wid >> 2) * 32;
    int wn = (wid & 3) * 16;

    float c[2][2][4];
    #pragma unroll
    for (int mf = 0; mf < 2; ++mf)
        #pragma unroll
        for (int nb = 0; nb < 2; ++nb)
            #pragma unroll
            for (int j = 0; j < 4; ++j) c[mf][nb][j] = 0.f;

    int ntiles = Kdim >> 6;

    auto issue = [&](int tt) {
        uint32_t sA = sbase + (uint32_t)(tt % NSTAGE) * STAGE_BYTES;
        uint32_t sB = sA + STAGE_A;
        int k0 = tt << 6;
        #pragma unroll
        for (int i = 0; i < 2; ++i) {
            int id = tid + i * 256;
            int row = id >> 3, c16 = id & 7;
            cpa16(sA + (uint32_t)(row * PITCH_B + c16 * 16),
                  A + (size_t)(m0 + row) * Kdim + k0 + c16 * 8);
        }
        #pragma unroll
        for (int i = 0; i < 2; ++i) {
            int id = tid + i * 256;
            int row = id >> 3, c16 = id & 7;
            cpa16(sB + (uint32_t)(row * PITCH_B + c16 * 16),
                  B + (size_t)(k0 + row) * 2048 + n0 + c16 * 8);
        }
        asm volatile("cp.async.commit_group;\n" ::: "memory");
    };

    issue(0);
    issue(1);

    for (int tt = 0; tt < ntiles; ++tt) {
        asm volatile("cp.async.wait_group 1;\n" ::: "memory");
        __syncthreads();
        if (tt + 2 < ntiles) issue(tt + 2);
        else asm volatile("cp.async.commit_group;\n" ::: "memory");

        uint32_t sA = sbase + (uint32_t)(tt % NSTAGE) * STAGE_BYTES;
        uint32_t sB = sA + STAGE_A;
        #pragma unroll
        for (int ks = 0; ks < 4; ++ks) {
            uint32_t a[2][4], b[4];
            #pragma unroll
            for (int mf = 0; mf < 2; ++mf)
                ldm_x4(a[mf], sA + (uint32_t)((wm + mf * 16 + (lane & 15)) * PITCH_B
                                              + (ks * 16 + ((lane >> 4) << 3)) * 2));
            ldm_x4t(b, sB + (uint32_t)((ks * 16 + (lane & 15)) * PITCH_B
                                       + (wn + ((lane >> 4) << 3)) * 2));
            #pragma unroll
            for (int mf = 0; mf < 2; ++mf) {
                mma16816(c[mf][0], a[mf], &b[0]);
                mma16816(c[mf][1], a[mf], &b[2]);
            }
        }
    }

    // epilogue
    int tc = lane & 3, g = lane >> 2;
    #pragma unroll
    for (int mf = 0; mf < 2; ++mf)
        #pragma unroll
        for (int nb = 0; nb < 2; ++nb) {
            int col = n0 + wn + nb * 8 + tc * 2;
            #pragma unroll
            for (int half = 0; half < 2; ++half) {
                int row = m0 + wm + mf * 16 + g + half * 8;
                float v0 = c[mf][nb][half * 2 + 0];
                float v1 = c[mf][nb][half * 2 + 1];
                if (MODE == 1) {
                    float tw = tvec[row];
                    v0 += bias[col]     + tw * w1last[col];
                    v1 += bias[col + 1] + tw * w1last[col + 1];
                    v0 = (v0 >= 0.f) ? v0 : 0.01f * v0;
                    v1 = (v1 >= 0.f) ? v1 : 0.01f * v1;
                    *(__nv_bfloat162*)&g_h[(size_t)row * HDIM + col] =
                        __floats2bfloat162_rn(v0, v1);
                } else {
                    v0 += bias[col];
                    v1 += bias[col + 1];
                    *(float2*)&g_out[(size_t)row * NOUT + col] = make_float2(v0, v1);
                }
            }
        }
}

// ---------------- loss: EM closed form + fast erf, 1 elem/thread -----------------
__global__ void __launch_bounds__(256) loss_k(const float* __restrict__ x) {
    int blk = blockIdx.x;            // 1024 blocks
    int tid = threadIdx.x;
    int b = blk >> 2;
    int d = ((blk & 3) << 8) + tid;  // 0..1023
    float invg = g_invg[b], r = g_r[b], w = g_wgt[b];
    int lowt = g_lowt[b];

    float me = g_out[b * NOUT + d];
    float ls = g_out[b * NOUT + DDIM + d];
    float muv = g_mu[b * DDIM + d];
    float xv  = x[b * DDIM + d];

    const float IRP  = 0.5641895835f;          // 1/sqrt(pi)
    const float CH24 = 1.1283791671f / 24.0f;
    const float CH3  = 7.0f * 1.1283791671f / 5760.0f;

    float mu_x = muv * invg - r * me;
    float sx = r * __expf(ls);
    if (lowt) { mu_x = 0.f; sx = 1.f; }
    float inv  = 0.70710678118654752f / sx;
    float base = (-1.0f - mu_x) * inv;
    float h    = 0.015625f * inv;

    float S;
    if (h > 0.5f) {
        float center = 64.f * (1.f + mu_x);
        float halfw  = 256.f / inv;
        int klo = (int)ceilf(center - halfw);
        int khi = (int)floorf(center + halfw);
        klo = klo < 1 ? 1 : (klo > 127 ? 127 : klo);
        khi = khi < 0 ? 0 : (khi > 126 ? 126 : khi);
        S = (float)(126 - khi) - (float)(klo - 1);
        for (int k = klo; k <= khi; ++k)
            S += erf_fast(fmaf((float)k, h, base));
    } else {
        float a  = fmaf(0.5f,   h, base);
        float bq = fmaf(126.5f, h, base);
        float ea = __expf(-a * a);
        float eb = __expf(-bq * bq);
        float efa = erf_fast_e(a, ea), efb = erf_fast_e(bq, eb);
        float I = (bq * efb - a * efa) + IRP * (eb - ea);
        float rcp = 90.50966799f * sx;   // 1/h
        S = I * rcp
          - (h * CH24) * (eb - ea)
          + (h * h * h * CH3) * (fmaf(4.f * bq, bq, -2.f) * eb
                                 - fmaf(4.f * a, a, -2.f) * ea);
    }

    float G127 = 0.5f + 0.5f * erf_fast(fmaf(127.f, h, base));
    float pO = 0.9765625f * G127 - 0.015625f * (63.f + 0.5f * S);
    float diff = xv - pO;
    float acc = w * diff * diff;

    __shared__ float red[256];
    red[tid] = acc;
    __syncthreads();
    #pragma unroll
    for (int s = 128; s > 0; s >>= 1) {
        if (tid < s) red[tid] += red[tid + s];
        __syncthreads();
    }
    if (tid == 0) g_partial[blk] = red[0];
}

__global__ void finalize_k(float* __restrict__ out) {
    int tid = threadIdx.x;
    __shared__ double red[256];
    double s = 0.0;
    #pragma unroll
    for (int i = 0; i < 4; ++i) s += (double)g_partial[tid + i * 256];
    red[tid] = s;
    __syncthreads();
    #pragma unroll
    for (int st = 128; st > 0; st >>= 1) {
        if (tid < st) red[tid] += red[tid + st];
        __syncthreads();
    }
    if (tid == 0) out[0] = (float)(3.912023005428146 * red[0] / 262144.0);
}

// ---------------- launch --------------------------------------------------------
extern "C" void kernel_launch(void* const* d_in, const int* in_sizes, int n_in,
                              void* d_out, int out_size) {
    const float* x     = (const float*)d_in[0];   // (256,1024)
    const float* t     = (const float*)d_in[1];   // (256,1)
    const float* noise = (const float*)d_in[2];   // (256,1024)
    const float* W1    = (const float*)d_in[3];   // (1025,2048)
    const float* b1    = (const float*)d_in[4];   // (2048,)
    const float* W2    = (const float*)d_in[5];   // (2048,2048)
    const float* b2    = (const float*)d_in[6];   // (2048,)

    size_t smem = NSTAGE * STAGE_BYTES;   // 55296 > 48KB default -> opt-in required
    cudaFuncSetAttribute(gemm_k<1>, cudaFuncAttributeMaxDynamicSharedMemorySize, (int)smem);
    cudaFuncSetAttribute(gemm_k<2>, cudaFuncAttributeMaxDynamicSharedMemorySize, (int)smem);

    prep_k<<<2048, 256>>>(x, noise, t, W1);

    // gemm1: 128 gemm blocks + 2048 W2-converter blocks riding the idle SMs
    gemm_k<1><<<128 + 2048, 256, smem>>>(DDIM, b1, t, W1 + (size_t)DDIM * HDIM, W2);

    dim3 g2(2048 / 64, BROWS / 64);       // (32, 4) = 128 CTAs
    gemm_k<2><<<g2, 256, smem>>>(HDIM, b2, nullptr, nullptr, nullptr);

    loss_k<<<1024, 256>>>(x);
    finalize_k<<<1, 256>>>((float*)d_out);
}